// round 15
// baseline (speedup 1.0000x reference)
#include <cuda_runtime.h>

#define B_  8
#define C_  64
#define O_  64
#define H_  160
#define W_  160
#define HW_ (H_*W_)
#define OCOFF 18
#define CK  576      // C_ * 9
#define PIX 32

// K-chunking: 16 channels -> 144 K-rows per chunk, 4 chunks
#define MCH_C    16
#define MCH_ROWS 144
#define N_MCH    (C_ / MCH_C)      // 4 chunks

// ---------------------------------------------------------------------------
// Fused kernel: offset conv (18ch) + deform sample + implicit GEMM (O=64,
// K=576, 4 x 144-row chunks) + BN + ReLU. Block: 128 threads, 32-pixel tile.
// R10: higher output-reuse tiles to halve smem-read (l1tex) traffic:
//   offset GEMM: 4 warps x 1px, 4-5 outputs/thread (scalar LDS.32)
//   main GEMM:   8o x 2p per thread (LDS.64 cols)
// ---------------------------------------------------------------------------
__global__ __launch_bounds__(128) void fused_deform_kernel(
    const float* __restrict__ x,
    const float* __restrict__ w_off,
    const float* __restrict__ b_off,
    const float* __restrict__ w_dcn,
    const float* __restrict__ b_dcn,
    const float* __restrict__ gamma,
    const float* __restrict__ beta,
    const float* __restrict__ run_mean,
    const float* __restrict__ run_var,
    float* __restrict__ out)
{
    __shared__ float  buf[MCH_ROWS * PIX];   // [144][32] = 18432 B (im2col / cols)
    __shared__ int    idxp[9 * PIX];         // 1152 B (packed indices)
    __shared__ float4 wt4[9 * PIX];          // 4608 B (wy0',wy1',wx0',wx1')
    __shared__ float  off_s[OCOFF * PIX];    // 2304 B (offset tile)
    __shared__ float  scale_s[O_];
    __shared__ float  shift_s[O_];

    const int b  = blockIdx.z;
    const int h  = blockIdx.y;
    const int w0 = blockIdx.x * PIX;
    const int tid = threadIdx.x;

    // ---- Phase 0: BN scale/shift (b_dcn folded in)
    if (tid < 64) {
        const float inv = __ldg(gamma + tid) * rsqrtf(__ldg(run_var + tid) + 1e-5f);
        scale_s[tid] = inv;
        shift_s[tid] = __ldg(beta + tid) + (__ldg(b_dcn + tid) - __ldg(run_mean + tid)) * inv;
    }

    // ---- Phase 1: offset conv. Thread (warp og1, lane p1): outputs
    // o = 4*og1+{0..3} (+ 16+og1 for og1<2) at single pixel p1.
    const int og1 = tid >> 5;       // warp id 0..3
    const int p1  = tid & 31;

    float oacc[5] = {0.f, 0.f, 0.f, 0.f, 0.f};

    const float4* wo4 = (const float4*)w_off;   // [18][144] of float4
    const float*  xb  = x + b * C_ * HW_;

    for (int ch = 0; ch < N_MCH; ch++) {
        const int c0 = ch * MCH_C;
        // im2col chunk: buf[cl*9+k][p] = x[b,c0+cl,h+ky-1,w0+p+kx-1]
        for (int j = tid; j < MCH_ROWS * PIX; j += 128) {
            const int p   = j & 31;
            const int idx = j >> 5;            // local row 0..143
            const int cl  = idx / 9;
            const int k   = idx - cl * 9;
            const int row = h + (k / 3) - 1;
            const int col = w0 + p + (k % 3) - 1;
            float v = 0.0f;
            if (row >= 0 && row < H_ && col >= 0 && col < W_)
                v = __ldg(xb + (c0 + cl) * HW_ + row * W_ + col);
            buf[idx * PIX + p] = v;
        }
        __syncthreads();

        const int wbase = ch * 36;             // chunk offset in float4 units
        #pragma unroll 4
        for (int ii = 0; ii < MCH_ROWS; ii += 4) {
            const float c0v = buf[(ii + 0) * PIX + p1];
            const float c1v = buf[(ii + 1) * PIX + p1];
            const float c2v = buf[(ii + 2) * PIX + p1];
            const float c3v = buf[(ii + 3) * PIX + p1];
            #pragma unroll
            for (int q = 0; q < 4; q++) {
                const float4 wa = __ldg(wo4 + (4 * og1 + q) * 144 + wbase + (ii >> 2));
                oacc[q] += wa.x * c0v + wa.y * c1v + wa.z * c2v + wa.w * c3v;
            }
            if (og1 < 2) {
                const float4 wc = __ldg(wo4 + (16 + og1) * 144 + wbase + (ii >> 2));
                oacc[4] += wc.x * c0v + wc.y * c1v + wc.z * c2v + wc.w * c3v;
            }
        }
        __syncthreads();
    }

    // ---- Phase 2: offsets to smem (+ bias)
    {
        #pragma unroll
        for (int q = 0; q < 4; q++) {
            const int o = 4 * og1 + q;
            off_s[o * PIX + p1] = oacc[q] + __ldg(b_off + o);
        }
        if (og1 < 2) {
            const int o = 16 + og1;
            off_s[o * PIX + p1] = oacc[4] + __ldg(b_off + o);
        }
    }
    __syncthreads();

    // ---- Phase 3: tap metadata for 32 pixels x 9 kernel positions
    for (int j = tid; j < 9 * PIX; j += 128) {
        const int k = j >> 5;
        const int p = j & 31;
        const float offy = off_s[(2 * k)     * PIX + p];
        const float offx = off_s[(2 * k + 1) * PIX + p];
        const float py = (float)(h + k / 3 - 1) + offy;
        const float px = (float)(w0 + p + (k % 3) - 1) + offx;
        const float y0f = floorf(py);
        const float x0f = floorf(px);
        const float fy = py - y0f;
        const float fx = px - x0f;
        const int iy0 = (int)y0f, iy1 = iy0 + 1;
        const int ix0 = (int)x0f, ix1 = ix0 + 1;
        const bool vy0 = (iy0 >= 0) && (iy0 < H_);
        const bool vy1 = (iy1 >= 0) && (iy1 < H_);
        const bool vx0 = (ix0 >= 0) && (ix0 < W_);
        const bool vx1 = (ix1 >= 0) && (ix1 < W_);
        float4 wv;
        wv.x = vy0 ? (1.0f - fy) : 0.0f;   // wy0'
        wv.y = vy1 ? fy          : 0.0f;   // wy1'
        wv.z = vx0 ? (1.0f - fx) : 0.0f;   // wx0'
        wv.w = vx1 ? fx          : 0.0f;   // wx1'
        wt4[j] = wv;
        const int iy0c = min(max(iy0, 0), H_ - 1);
        const int iy1c = min(max(iy1, 0), H_ - 1);
        const int ix0c = min(max(ix0, 0), W_ - 1);
        const int ix1c = min(max(ix1, 0), W_ - 1);
        const int base = iy0c * W_ + ix0c;           // <= 25599, fits 15 bits
        const int dx   = ix1c - ix0c;                // 0 or 1
        const int dy   = iy1c - iy0c;                // 0 or 1
        idxp[j] = base | (dx << 15) | (dy << 16);
    }
    __syncthreads();

    // ---- Phase 4: sampling + main GEMM, 8o x 2p per thread
    const int og = tid >> 4;        // 0..7  -> o base = 8*og
    const int pg = tid & 15;        // 0..15 -> p base = 2*pg
    const int p  = tid & 31;        // sampling lane = pixel
    const int cg = tid >> 5;        // 0..3 channel group

    float acc[8][2];
    #pragma unroll
    for (int i = 0; i < 8; i++) { acc[i][0] = 0.0f; acc[i][1] = 0.0f; }

    const float4* w4  = (const float4*)w_dcn;    // [64][144] of float4
    const float2* c2b = (const float2*)buf;      // [144][16] of float2
    const int obase = og * 8;

    for (int ch = 0; ch < N_MCH; ch++) {
        const int c0 = ch * MCH_C;

        // ---- sample 16 channels x 9 taps x 32 pixels into buf[cl*9+k][p]
        #pragma unroll
        for (int k = 0; k < 9; k++) {
            const int j = k * 32 + p;
            const int   pk = idxp[j];
            const float4 wv = wt4[j];
            const int base = pk & 0x7FFF;
            const int dx   = (pk >> 15) & 1;
            const int dW   = ((pk >> 16) & 1) * W_;
            const int i00 = base;
            const int i01 = base + dx;
            const int i10 = base + dW;
            const int i11 = i10 + dx;
            #pragma unroll
            for (int cl = cg; cl < MCH_C; cl += 4) {    // 4 iterations
                const float* xc = xb + (c0 + cl) * HW_;
                const float g00 = __ldg(xc + i00);
                const float g01 = __ldg(xc + i01);
                const float g10 = __ldg(xc + i10);
                const float g11 = __ldg(xc + i11);
                const float v = wv.x * (wv.z * g00 + wv.w * g01)
                              + wv.y * (wv.z * g10 + wv.w * g11);
                buf[(cl * 9 + k) * PIX + p] = v;
            }
        }
        __syncthreads();

        // ---- GEMM accumulate over this K-slice (144 rows)
        const int wbase = ch * 36;                      // float4 units
        #pragma unroll 2
        for (int ii = 0; ii < MCH_ROWS; ii += 4) {
            float2 cv[4];
            #pragma unroll
            for (int r = 0; r < 4; r++) cv[r] = c2b[(ii + r) * 16 + pg];
            #pragma unroll
            for (int oo = 0; oo < 8; oo++) {
                const float4 wv = __ldg(w4 + (obase + oo) * 144 + wbase + (ii >> 2));
                acc[oo][0] += wv.x * cv[0].x + wv.y * cv[1].x + wv.z * cv[2].x + wv.w * cv[3].x;
                acc[oo][1] += wv.x * cv[0].y + wv.y * cv[1].y + wv.z * cv[2].y + wv.w * cv[3].y;
            }
        }
        __syncthreads();
    }

    // ---- Epilogue: BN affine + ReLU, float2 store (2 consecutive pixels)
    const int pbase = h * W_ + w0 + 2 * pg;
    #pragma unroll
    for (int oo = 0; oo < 8; oo++) {
        const int o = obase + oo;
        const float s  = scale_s[o];
        const float sh = shift_s[o];
        float2 r;
        r.x = fmaxf(acc[oo][0] * s + sh, 0.0f);
        r.y = fmaxf(acc[oo][1] * s + sh, 0.0f);
        *(float2*)(out + (b * O_ + o) * HW_ + pbase) = r;
    }
}

// ---------------------------------------------------------------------------
extern "C" void kernel_launch(void* const* d_in, const int* in_sizes, int n_in,
                              void* d_out, int out_size)
{
    const float* x        = (const float*)d_in[0];
    const float* w_off    = (const float*)d_in[1];
    const float* b_off    = (const float*)d_in[2];
    const float* w_dcn    = (const float*)d_in[3];
    const float* b_dcn    = (const float*)d_in[4];
    const float* gamma    = (const float*)d_in[5];
    const float* beta     = (const float*)d_in[6];
    const float* run_mean = (const float*)d_in[7];
    const float* run_var  = (const float*)d_in[8];
    float* out = (float*)d_out;

    dim3 grid(W_ / PIX, H_, B_);   // 5 x 160 x 8 = 6400 blocks

    fused_deform_kernel<<<grid, 128>>>(x, w_off, b_off, w_dcn, b_dcn,
                                       gamma, beta, run_mean, run_var, out);
}